// round 8
// baseline (speedup 1.0000x reference)
#include <cuda_runtime.h>
#include <math.h>

// ---------------------------------------------------------------------------
// Mie scattering, table-based v3:
//   1) reduce:  x_mean partials (float4 x8 unrolled, deterministic)
//   2) coeff:   a_n,b_n in double (reciprocal-multiply recurrences) ->
//               folded fp32 p_n,q_n
//   3) table:   I(theta) on 2048-interval grid, fp32 reference recurrence,
//               written as float4-packed entries (taps j..j+3)
//   4) main:    persistent grid (6 blocks/SM), cubic Lagrange from
//               float4-packed smem table (1 LDS.128/elem)
// ---------------------------------------------------------------------------

#define N_TERMS    50
#define RED_BLOCKS 576
#define RED_THREADS 256
#define TABLE_N    2048                 // intervals over [0, pi]
#define TABLE_PTS  (TABLE_N + 4)        // scalar points 0..2051
#define TABLE_ENTRIES (TABLE_N + 1)     // float4 entries 0..2048
#define MAIN_BLOCKS 888                 // 6 resident blocks x 148 SMs

static __device__ double g_partials[RED_BLOCKS];
static __device__ float4 g_pq[N_TERMS];        // fp32 (p.re, p.im, q.re, q.im)
static __device__ float4 g_table4[TABLE_ENTRIES];

// ---------------- Stage 1: partial sums of x = pi*d/lambda ------------------
__global__ void mie_reduce_kernel(const float* __restrict__ d, int n) {
    __shared__ double sh[RED_THREADS];
    float a0 = 0.f, a1 = 0.f, a2 = 0.f, a3 = 0.f;
    int n4 = n >> 2;
    const float4* __restrict__ d4 = (const float4*)d;
    int T   = gridDim.x * blockDim.x;
    int gid = blockIdx.x * blockDim.x + threadIdx.x;

    if (n4 == T * 8) {                 // benchmark shape: exactly 8 float4/thread
#pragma unroll
        for (int k = 0; k < 8; k++) {
            float4 v = d4[gid + k * T];
            a0 += __fdiv_rn(__fmul_rn(3.14159274101257324f, v.x), 5.5e-7f);
            a1 += __fdiv_rn(__fmul_rn(3.14159274101257324f, v.y), 5.5e-7f);
            a2 += __fdiv_rn(__fmul_rn(3.14159274101257324f, v.z), 5.5e-7f);
            a3 += __fdiv_rn(__fmul_rn(3.14159274101257324f, v.w), 5.5e-7f);
        }
    } else {
        for (int i = gid; i < n4; i += T) {
            float4 v = d4[i];
            a0 += __fdiv_rn(__fmul_rn(3.14159274101257324f, v.x), 5.5e-7f);
            a1 += __fdiv_rn(__fmul_rn(3.14159274101257324f, v.y), 5.5e-7f);
            a2 += __fdiv_rn(__fmul_rn(3.14159274101257324f, v.z), 5.5e-7f);
            a3 += __fdiv_rn(__fmul_rn(3.14159274101257324f, v.w), 5.5e-7f);
        }
        for (int i = (n4 << 2) + gid; i < n; i += T)
            a0 += __fdiv_rn(__fmul_rn(3.14159274101257324f, d[i]), 5.5e-7f);
    }

    sh[threadIdx.x] = ((double)a0 + (double)a1) + ((double)a2 + (double)a3);
    __syncthreads();
    for (int s = RED_THREADS / 2; s > 0; s >>= 1) {
        if (threadIdx.x < s) sh[threadIdx.x] += sh[threadIdx.x + s];
        __syncthreads();
    }
    if (threadIdx.x == 0) g_partials[blockIdx.x] = sh[0];
}

// ---------------- Stage 2: mean + Mie coefficients (double, no div chain) ---
__global__ void mie_coeff_kernel(int n_total) {
    __shared__ double sh[64];
    __shared__ double jx[N_TERMS + 1], yx[N_TERMS + 1], jmx[N_TERMS + 1];
    __shared__ double shx, shmx, sinvx, sinvmx;
    int t = threadIdx.x;

    double s = 0.0;
    for (int i = t; i < RED_BLOCKS; i += 64) s += g_partials[i];
    sh[t] = s;
    __syncthreads();
    for (int w = 32; w > 0; w >>= 1) {
        if (t < w) sh[t] += sh[t + w];
        __syncthreads();
    }

    if (t == 0) {
        float xmf = (float)(sh[0] / (double)n_total);   // fp32 mean like jnp
        float mxf = __fmul_rn(1.31f, xmf);              // fp32 m*x
        double x  = (double)xmf;
        double mx = (double)mxf;
        double invx  = 1.0 / x;          // hoisted: only 2 fp64 divides here
        double invmx = 1.0 / mx;
        shx = x; shmx = mx; sinvx = invx; sinvmx = invmx;

        double sx = sin(x),  cx = cos(x);
        double smx = sin(mx), cmx = cos(mx);
        jx[0]  = sx * invx;
        jx[1]  = sx * invx * invx - cx * invx;
        yx[0]  = -cx * invx;
        yx[1]  = -cx * invx * invx - sx * invx;
        jmx[0] = smx * invmx;
        jmx[1] = smx * invmx * invmx - cmx * invmx;
        for (int k = 1; k < N_TERMS; k++) {
            double c  = (2.0 * k + 1.0) * invx;
            double cm = (2.0 * k + 1.0) * invmx;
            jx[k + 1]  = c  * jx[k]  - jx[k - 1];
            yx[k + 1]  = c  * yx[k]  - yx[k - 1];
            jmx[k + 1] = cm * jmx[k] - jmx[k - 1];
        }
    }
    __syncthreads();

    if (t < N_TERMS) {
        int n = t + 1;
        double dn = (double)n;
        double x = shx, invx = sinvx, invmx = sinvmx;
        double m = (double)1.31f;

        double jn  = jx[n],  jn1 = jx[n - 1];
        double yn  = yx[n],  yn1 = yx[n - 1];
        double jm  = jmx[n], jm1 = jmx[n - 1];

        double dj = jm1 - (dn + 1.0) * invmx * jm;
        double D  = dj / (jm + 1e-10);

        double psi  = x * jn,  psi1 = x * jn1;
        double chi  = x * yn,  chi1 = x * yn1;   // xi = psi + i*chi

        double nx = dn * invx;
        double fa = D / m + nx;
        double fb = m * D + nx;

        double numa = fa * psi - psi1;
        double dar  = numa + 1e-10;
        double dai  = fa * chi - chi1;
        double ia   = 1.0 / (dar * dar + dai * dai);
        double ar   = numa * dar * ia;
        double ai   = -numa * dai * ia;

        double numb = fb * psi - psi1;
        double dbr  = numb + 1e-10;
        double dbi  = fb * chi - chi1;
        double ib   = 1.0 / (dbr * dbr + dbi * dbi);
        double br   = numb * dbr * ib;
        double bi   = -numb * dbi * ib;

        double cc = 0.5 * (2.0 * dn + 1.0) / (dn * (dn + 1.0));
        g_pq[t] = make_float4((float)(cc * (ar + br)), (float)(cc * (ai + bi)),
                              (float)(cc * (ar - br)), (float)(cc * (ai - bi)));
    }
}

// ---------------- Stage 3: build I(theta) table (fp32, float4-packed) -------
__global__ void mie_table_kernel() {
    int i = blockIdx.x * blockDim.x + threadIdx.x;
    if (i >= TABLE_PTS) return;

    const double H = 3.14159265358979323846 / (double)TABLE_N;
    double thd = (double)i * H;
    float c  = (float)cos(thd);
    float st = (float)sin(thd) + 1e-10f;
    float inv_s = 1.0f / st;
    float pi1 = -sqrtf(fmaxf(1.0f - c * c, 0.0f)) * inv_s;

    // n = 1: tau_1 = c (reference's where-branch)
    float4 w = g_pq[0];
    float u = pi1 + c, v = pi1 - c;
    float Ar = w.x * u, Ai = w.y * u;
    float Br = w.z * v, Bi = w.w * v;

    float qp = pi1;               // pi_{n-1}
    float qc = 3.0f * c * pi1;    // pi_2  (pi_0 = 0)

#pragma unroll
    for (int n = 2; n <= N_TERMS; n++) {
        const float nf   = (float)n;
        const float np1  = (float)(n + 1);
        const float invn = 1.0f / (float)n;   // compile-time constant

        float t1 = c * qc;
        float ta = fmaf(nf, t1, -np1 * qp);   // tau_n
        float uu = qc + ta;
        float vv = qc - ta;

        w = g_pq[n - 1];
        Ar = fmaf(w.x, uu, Ar);
        Ai = fmaf(w.y, uu, Ai);
        Br = fmaf(w.z, vv, Br);
        Bi = fmaf(w.w, vv, Bi);

        float qn = fmaf(np1, t1, ta) * invn;  // pi_{n+1}
        qp = qc; qc = qn;
    }

    const float SCALE = (float)(5.5e-7 * 5.5e-7 /
        (4.0 * 3.14159265358979323846 * 3.14159265358979323846));
    float val = (Ar * Ar + Ai * Ai + Br * Br + Bi * Bi) * SCALE;

    // scatter this point into the 4 float4 entries that reference it:
    // entry j holds taps (j, j+1, j+2, j+3); point i lands in entry i-c slot c.
#pragma unroll
    for (int cidx = 0; cidx < 4; cidx++) {
        int j = i - cidx;
        if (j >= 0 && j < TABLE_ENTRIES)
            ((float*)&g_table4[j])[cidx] = val;
    }
}

// ---------------- Stage 4: cubic Lagrange from float4-packed table ----------
__device__ __forceinline__ float interp4(const float4* __restrict__ T,
                                         float th, float inv_h) {
    float t  = th * inv_h;
    float jf = floorf(t);
    float s  = t - jf;
    int j = (int)jf - 1;
    j = min(max(j, 0), TABLE_N);           // entries 0..TABLE_N

    float4 v = T[j];                        // one LDS.128: taps j..j+3
    float sm1 = s + 1.0f, s1 = s - 1.0f, s2 = s - 2.0f;
    float a = s * s1;
    float b = sm1 * s2;
    float w0 = -0.16666667f * (a * s2);
    float w1 =  0.5f        * (b * s1);
    float w2 = -0.5f        * (b * s);
    float w3 =  0.16666667f * (sm1 * a);
    return fmaf(w0, v.x, fmaf(w1, v.y, fmaf(w2, v.z, w3 * v.w)));
}

__global__ void __launch_bounds__(256) mie_main_kernel(
    const float* __restrict__ theta, float* __restrict__ out, int n)
{
    __shared__ float4 Ts4[TABLE_ENTRIES];   // 32.8 KB
    for (int i = threadIdx.x; i < TABLE_ENTRIES; i += 256)
        Ts4[i] = g_table4[i];               // coalesced LDG.128
    __syncthreads();

    const float INV_H = (float)TABLE_N / 3.14159265358979323846f;
    int n4 = n >> 2;
    const float4* __restrict__ th4 = (const float4*)theta;
    float4* __restrict__ out4 = (float4*)out;
    int stride = gridDim.x * blockDim.x;

    for (int i4 = blockIdx.x * blockDim.x + threadIdx.x; i4 < n4; i4 += stride) {
        float4 v = th4[i4];
        float4 r;
        r.x = interp4(Ts4, v.x, INV_H);
        r.y = interp4(Ts4, v.y, INV_H);
        r.z = interp4(Ts4, v.z, INV_H);
        r.w = interp4(Ts4, v.w, INV_H);
        out4[i4] = r;
    }

    // scalar remainder (n % 4), handled once by block 0
    if (blockIdx.x == 0 && threadIdx.x == 0) {
        for (int e = n4 << 2; e < n; e++)
            out[e] = interp4(Ts4, theta[e], INV_H);
    }
}

// ---------------------------------------------------------------------------
extern "C" void kernel_launch(void* const* d_in, const int* in_sizes, int n_in,
                              void* d_out, int out_size) {
    const float* d     = (const float*)d_in[0];
    const float* theta = (const float*)d_in[1];
    float* out = (float*)d_out;
    int n = in_sizes[0];

    mie_reduce_kernel<<<RED_BLOCKS, RED_THREADS>>>(d, n);
    mie_coeff_kernel<<<1, 64>>>(n);
    mie_table_kernel<<<(TABLE_PTS + 255) / 256, 256>>>();
    mie_main_kernel<<<MAIN_BLOCKS, 256>>>(theta, out, n);
}